// round 1
// baseline (speedup 1.0000x reference)
#include <cuda_runtime.h>
#include <cuda_bf16.h>

#define Hd   768
#define Bn   4
#define DECn 128
#define ENCn 512

// Scratch (allocation-free rule: __device__ globals)
__device__ float g_enc_t[Bn * ENCn * Hd];   // (B*ENC, H)
__device__ float g_dec_t[Bn * DECn * Hd];   // (B*DEC, H)

__device__ __forceinline__ float tanha(float x) {
    float y;
    asm("tanh.approx.f32 %0, %1;" : "=f"(y) : "f"(x));
    return y;
}

// ---------------------------------------------------------------------------
// GEMM: C[M,768] = A[M,768] @ W[768,768]   (W stored (in,out) i.e. K-major rows)
// BM=BN=64, BK=16, 256 threads, 4x4 register tile.
// ---------------------------------------------------------------------------
__global__ __launch_bounds__(256) void gemm_kernel(
    const float* __restrict__ A, const float* __restrict__ W,
    float* __restrict__ C, int M)
{
    const int K = Hd, N = Hd;
    __shared__ float As[16][65];   // [k][m], pad to dodge store conflicts
    __shared__ float Ws[16][64];   // [k][n]

    const int tid = threadIdx.x;
    const int bm  = blockIdx.y * 64;
    const int bn  = blockIdx.x * 64;

    const int arow = tid >> 2;            // 0..63
    const int acol = (tid & 3) << 2;      // 0,4,8,12
    const int wrow = tid >> 4;            // 0..15
    const int wcol = (tid & 15) << 2;     // 0..60
    const int tm   = (tid >> 4) << 2;     // 0..60
    const int tn   = (tid & 15) << 2;     // 0..60

    float acc[4][4];
#pragma unroll
    for (int i = 0; i < 4; i++)
#pragma unroll
        for (int j = 0; j < 4; j++) acc[i][j] = 0.f;

    const float* Ap = A + (size_t)(bm + arow) * K + acol;
    const float* Wp = W + (size_t)wrow * N + bn + wcol;

    for (int k0 = 0; k0 < K; k0 += 16) {
        float4 av = *(const float4*)(Ap + k0);
        float4 wv = *(const float4*)(Wp + (size_t)k0 * N);
        As[acol + 0][arow] = av.x;
        As[acol + 1][arow] = av.y;
        As[acol + 2][arow] = av.z;
        As[acol + 3][arow] = av.w;
        *(float4*)&Ws[wrow][wcol] = wv;
        __syncthreads();
#pragma unroll
        for (int kk = 0; kk < 16; kk++) {
            float a0 = As[kk][tm + 0];
            float a1 = As[kk][tm + 1];
            float a2 = As[kk][tm + 2];
            float a3 = As[kk][tm + 3];
            float4 bv = *(float4*)&Ws[kk][tn];
            acc[0][0] = fmaf(a0, bv.x, acc[0][0]);
            acc[0][1] = fmaf(a0, bv.y, acc[0][1]);
            acc[0][2] = fmaf(a0, bv.z, acc[0][2]);
            acc[0][3] = fmaf(a0, bv.w, acc[0][3]);
            acc[1][0] = fmaf(a1, bv.x, acc[1][0]);
            acc[1][1] = fmaf(a1, bv.y, acc[1][1]);
            acc[1][2] = fmaf(a1, bv.z, acc[1][2]);
            acc[1][3] = fmaf(a1, bv.w, acc[1][3]);
            acc[2][0] = fmaf(a2, bv.x, acc[2][0]);
            acc[2][1] = fmaf(a2, bv.y, acc[2][1]);
            acc[2][2] = fmaf(a2, bv.z, acc[2][2]);
            acc[2][3] = fmaf(a2, bv.w, acc[2][3]);
            acc[3][0] = fmaf(a3, bv.x, acc[3][0]);
            acc[3][1] = fmaf(a3, bv.y, acc[3][1]);
            acc[3][2] = fmaf(a3, bv.z, acc[3][2]);
            acc[3][3] = fmaf(a3, bv.w, acc[3][3]);
        }
        __syncthreads();
    }

    float* Cp = C + (size_t)(bm + tm) * N + bn + tn;
#pragma unroll
    for (int i = 0; i < 4; i++) {
        float4 o = make_float4(acc[i][0], acc[i][1], acc[i][2], acc[i][3]);
        *(float4*)(Cp + (size_t)i * N) = o;
    }
}

// ---------------------------------------------------------------------------
// Score kernel: out[b,d,e] = sum_k tanh(enc_t[b,e,k] + dec_t[b,d,k]) * vt[k]
// Block tile: 16 dec x 16 enc, one batch. 256 threads = 8 warps.
// Warp w owns dec rows {2w, 2w+1}; lanes span K (float4 -> 128 K per chunk);
// 8 enc pairs kept live in 32 accumulators.
// ---------------------------------------------------------------------------
__global__ __launch_bounds__(256) void score_kernel(
    const float* __restrict__ mask, const float* __restrict__ vt,
    float* __restrict__ out)
{
    extern __shared__ float sm[];
    float* dec_s = sm;              // 16*768
    float* enc_s = sm + 16 * Hd;    // 16*768
    float* vt_s  = sm + 32 * Hd;    // 768

    const int b  = blockIdx.z;
    const int dt = blockIdx.y * 16;
    const int et = blockIdx.x * 16;
    const int tid = threadIdx.x;

    const float* decg = g_dec_t + ((size_t)b * DECn + dt) * Hd;
    const float* encg = g_enc_t + ((size_t)b * ENCn + et) * Hd;

    // Cooperative tile loads (contiguous rows -> plain float4 streams)
    for (int i = tid; i < 16 * Hd / 4; i += 256)
        ((float4*)dec_s)[i] = ((const float4*)decg)[i];
    for (int i = tid; i < 16 * Hd / 4; i += 256)
        ((float4*)enc_s)[i] = ((const float4*)encg)[i];
    for (int i = tid; i < Hd / 4; i += 256)
        ((float4*)vt_s)[i] = ((const float4*)vt)[i];
    __syncthreads();

    const int warp = tid >> 5;
    const int lane = tid & 31;
    const int d0 = 2 * warp;   // local dec row pair

    float acc[8][4];
#pragma unroll
    for (int ep = 0; ep < 8; ep++)
#pragma unroll
        for (int q = 0; q < 4; q++) acc[ep][q] = 0.f;

    const float* dp0 = dec_s + (size_t)d0 * Hd;
    const float* dp1 = dec_s + (size_t)(d0 + 1) * Hd;

#pragma unroll 1
    for (int c = 0; c < 6; c++) {                 // 6 chunks of 128 K
        const int k = c * 128 + lane * 4;
        float4 a0 = *(const float4*)(dp0 + k);
        float4 a1 = *(const float4*)(dp1 + k);
        float4 v  = *(const float4*)(vt_s + k);
#pragma unroll
        for (int ep = 0; ep < 8; ep++) {
            float4 b0 = *(const float4*)(enc_s + (size_t)(2 * ep) * Hd + k);
            float4 b1 = *(const float4*)(enc_s + (size_t)(2 * ep + 1) * Hd + k);
            // (d0,e0)
            acc[ep][0] = fmaf(tanha(a0.x + b0.x), v.x, acc[ep][0]);
            acc[ep][0] = fmaf(tanha(a0.y + b0.y), v.y, acc[ep][0]);
            acc[ep][0] = fmaf(tanha(a0.z + b0.z), v.z, acc[ep][0]);
            acc[ep][0] = fmaf(tanha(a0.w + b0.w), v.w, acc[ep][0]);
            // (d0,e1)
            acc[ep][1] = fmaf(tanha(a0.x + b1.x), v.x, acc[ep][1]);
            acc[ep][1] = fmaf(tanha(a0.y + b1.y), v.y, acc[ep][1]);
            acc[ep][1] = fmaf(tanha(a0.z + b1.z), v.z, acc[ep][1]);
            acc[ep][1] = fmaf(tanha(a0.w + b1.w), v.w, acc[ep][1]);
            // (d1,e0)
            acc[ep][2] = fmaf(tanha(a1.x + b0.x), v.x, acc[ep][2]);
            acc[ep][2] = fmaf(tanha(a1.y + b0.y), v.y, acc[ep][2]);
            acc[ep][2] = fmaf(tanha(a1.z + b0.z), v.z, acc[ep][2]);
            acc[ep][2] = fmaf(tanha(a1.w + b0.w), v.w, acc[ep][2]);
            // (d1,e1)
            acc[ep][3] = fmaf(tanha(a1.x + b1.x), v.x, acc[ep][3]);
            acc[ep][3] = fmaf(tanha(a1.y + b1.y), v.y, acc[ep][3]);
            acc[ep][3] = fmaf(tanha(a1.z + b1.z), v.z, acc[ep][3]);
            acc[ep][3] = fmaf(tanha(a1.w + b1.w), v.w, acc[ep][3]);
        }
    }

    // Warp-reduce each accumulator across lanes (K partials)
#pragma unroll
    for (int ep = 0; ep < 8; ep++)
#pragma unroll
        for (int q = 0; q < 4; q++) {
#pragma unroll
            for (int off = 16; off > 0; off >>= 1)
                acc[ep][q] += __shfl_xor_sync(0xFFFFFFFFu, acc[ep][q], off);
        }

    if (lane == 0) {
        const size_t half = (size_t)Bn * DECn * ENCn;
#pragma unroll
        for (int ep = 0; ep < 8; ep++) {
#pragma unroll
            for (int q = 0; q < 4; q++) {
                const int di = q >> 1;
                const int ei = q & 1;
                const int d = dt + d0 + di;
                const int e = et + 2 * ep + ei;
                const size_t idx = ((size_t)b * DECn + d) * ENCn + e;
                const float raw = acc[ep][q];
                out[idx]        = raw + mask[idx];
                out[half + idx] = raw;
            }
        }
    }
}

// ---------------------------------------------------------------------------
extern "C" void kernel_launch(void* const* d_in, const int* in_sizes, int n_in,
                              void* d_out, int out_size)
{
    const float* dec  = (const float*)d_in[0];   // (4,128,768)
    const float* enc  = (const float*)d_in[1];   // (4,512,768)
    const float* mask = (const float*)d_in[2];   // (4,128,512)
    const float* W1   = (const float*)d_in[3];   // (768,768)
    const float* W2   = (const float*)d_in[4];   // (768,768)
    const float* vt   = (const float*)d_in[5];   // (768,)
    float* out = (float*)d_out;

    float *enc_t_ptr, *dec_t_ptr;
    cudaGetSymbolAddress((void**)&enc_t_ptr, g_enc_t);
    cudaGetSymbolAddress((void**)&dec_t_ptr, g_dec_t);

    // enc_t = encoder_outputs @ W1 : M = 4*512 = 2048
    gemm_kernel<<<dim3(Hd / 64, (Bn * ENCn) / 64), 256>>>(enc, W1, enc_t_ptr, Bn * ENCn);
    // dec_t = decoder_state @ W2 : M = 4*128 = 512
    gemm_kernel<<<dim3(Hd / 64, (Bn * DECn) / 64), 256>>>(dec, W2, dec_t_ptr, Bn * DECn);

    // Fused tanh-score + mask, dual output
    const int smem_bytes = (32 * Hd + Hd) * sizeof(float);   // 101376
    cudaFuncSetAttribute(score_kernel, cudaFuncAttributeMaxDynamicSharedMemorySize, smem_bytes);
    score_kernel<<<dim3(ENCn / 16, DECn / 16, Bn), 256, smem_bytes>>>(mask, vt, out);
}

// round 4
// speedup vs baseline: 1.5465x; 1.5465x over previous
#include <cuda_runtime.h>
#include <cuda_bf16.h>
#include <cstdint>

#define Hd   768
#define Bn   4
#define DECn 128
#define ENCn 512
#define K2   1536          // stored split K (hi | lo)
#define MROWS (Bn*ENCn + Bn*DECn)   // 2560

// ---------------- scratch (__device__ globals; no allocs allowed) ----------
__device__ float          g_enc_t[Bn * ENCn * Hd];
__device__ float          g_dec_t[Bn * DECn * Hd];
__device__ __nv_bfloat16  g_in_split[MROWS * K2];
__device__ __nv_bfloat16  g_w1t[Hd * K2];   // W1^T split: [n][hi(768)|lo(768)]
__device__ __nv_bfloat16  g_w2t[Hd * K2];   // W2^T split

__device__ __forceinline__ float tanha(float x) {
    float y;
    asm("tanh.approx.f32 %0, %1;" : "=f"(y) : "f"(x));
    return y;
}

__device__ __forceinline__ uint32_t smem_u32(const void* p) {
    return (uint32_t)__cvta_generic_to_shared(p);
}

__device__ __forceinline__ void ldm_x4(uint32_t addr, uint32_t* r) {
    asm volatile("ldmatrix.sync.aligned.m8n8.x4.shared.b16 {%0,%1,%2,%3}, [%4];"
        : "=r"(r[0]), "=r"(r[1]), "=r"(r[2]), "=r"(r[3]) : "r"(addr));
}

__device__ __forceinline__ void mma16816(float* d, const uint32_t* a, const uint32_t* b) {
    asm volatile("mma.sync.aligned.m16n8k16.row.col.f32.bf16.bf16.f32 "
        "{%0,%1,%2,%3}, {%4,%5,%6,%7}, {%8,%9}, {%0,%1,%2,%3};"
        : "+f"(d[0]), "+f"(d[1]), "+f"(d[2]), "+f"(d[3])
        : "r"(a[0]), "r"(a[1]), "r"(a[2]), "r"(a[3]), "r"(b[0]), "r"(b[1]));
}

// ---------------------------------------------------------------------------
// fp32 -> bf16 hi|lo split, rows x 768 -> rows x 1536  ([hi(768) | lo(768)])
// ---------------------------------------------------------------------------
__global__ __launch_bounds__(256) void split_kernel(
    const float* __restrict__ src, __nv_bfloat16* __restrict__ dst, int rows)
{
    int i = blockIdx.x * 256 + threadIdx.x;
    int total = rows * (Hd / 4);
    if (i >= total) return;
    int row = i / (Hd / 4);
    int c4  = (i % (Hd / 4)) * 4;
    float4 v = *(const float4*)(src + (size_t)row * Hd + c4);
    __nv_bfloat16 h0 = __float2bfloat16(v.x), h1 = __float2bfloat16(v.y);
    __nv_bfloat16 h2 = __float2bfloat16(v.z), h3 = __float2bfloat16(v.w);
    float l0 = v.x - __bfloat162float(h0), l1 = v.y - __bfloat162float(h1);
    float l2 = v.z - __bfloat162float(h2), l3 = v.w - __bfloat162float(h3);
    __nv_bfloat16* dh = dst + (size_t)row * K2 + c4;
    __nv_bfloat16* dl = dh + Hd;
    *(__nv_bfloat162*)(dh)     = __nv_bfloat162(h0, h1);
    *(__nv_bfloat162*)(dh + 2) = __nv_bfloat162(h2, h3);
    *(__nv_bfloat162*)(dl)     = __floats2bfloat162_rn(l0, l1);
    *(__nv_bfloat162*)(dl + 2) = __floats2bfloat162_rn(l2, l3);
}

// W (768 k x 768 n, k-major rows) -> transposed split dst[n][k'] = hi|lo
__global__ __launch_bounds__(256) void wsplit_kernel(
    const float* __restrict__ W, __nv_bfloat16* __restrict__ dst)
{
    __shared__ float t[32][33];
    int k0 = blockIdx.y * 32, n0 = blockIdx.x * 32;
    int tx = threadIdx.x, ty = threadIdx.y;   // 32 x 8
#pragma unroll
    for (int j = 0; j < 4; j++)
        t[ty + j * 8][tx] = W[(size_t)(k0 + ty + j * 8) * Hd + n0 + tx];
    __syncthreads();
#pragma unroll
    for (int j = 0; j < 4; j++) {
        int n = n0 + ty + j * 8;
        int k = k0 + tx;
        float x = t[tx][ty + j * 8];
        __nv_bfloat16 h = __float2bfloat16(x);
        float l = x - __bfloat162float(h);
        dst[(size_t)n * K2 + k]      = h;
        dst[(size_t)n * K2 + Hd + k] = __float2bfloat16(l);
    }
}

// ---------------------------------------------------------------------------
// Tensor-core GEMM via mma.sync, 3-term bf16 split:
//   C = ah*bh + al*bh + ah*bl   (al*bl ~2^-18, dropped)
// 72 K-chunks of 32; chunk c phase p=c/24: p0=(ah,bh) p1=(al,bh) p2=(ah,bl).
// Tile 128x128, 8 warps (4m x 2n), warp tile 32x64; 80B-padded SMEM rows
// (conflict-free ldmatrix: row stride 20 words tiles all 32 banks).
// ---------------------------------------------------------------------------
#define BK       32
#define ROWB     80
#define NCK      72

__device__ __forceinline__ void chunk_off(int c, int& ao, int& bo) {
    const int phase = c / 24;
    const int r     = c - phase * 24;
    const int base  = r * (BK * 2);        // bytes
    ao = base + (phase == 1 ? Hd * 2 : 0);
    bo = base + (phase == 2 ? Hd * 2 : 0);
}

__global__ __launch_bounds__(256, 1)
void gemm_tc_mma(const __nv_bfloat16* __restrict__ Asp,
                 const __nv_bfloat16* __restrict__ W1sp,
                 const __nv_bfloat16* __restrict__ W2sp,
                 float* __restrict__ Cenc, float* __restrict__ Cdec)
{
    __shared__ __align__(16) char sAs[128 * ROWB];
    __shared__ __align__(16) char sBs[128 * ROWB];

    const int tid    = threadIdx.x;
    const int wid    = tid >> 5;
    const int lane   = tid & 31;
    const int warp_m = wid & 3;
    const int warp_n = wid >> 2;

    const int tileN = blockIdx.x * 128;
    const int mt    = blockIdx.y * 128;
    const __nv_bfloat16* Bsp;
    float* C; int crow;
    if (mt < Bn * ENCn) { Bsp = W1sp; C = Cenc; crow = mt; }
    else                { Bsp = W2sp; C = Cdec; crow = mt - Bn * ENCn; }

    const char* Agb = (const char*)(Asp + (size_t)mt   * K2);
    const char* Bgb = (const char*)(Bsp + (size_t)tileN * K2);

    const uint32_t sA = smem_u32(sAs);
    const uint32_t sB = smem_u32(sBs);

    const int r0 = tid >> 2, q0 = tid & 3;
    const int r1 = (256 + tid) >> 2, q1 = tid & 3;

    float acc[2][8][4];
#pragma unroll
    for (int a = 0; a < 2; a++)
#pragma unroll
        for (int b = 0; b < 8; b++)
#pragma unroll
            for (int c = 0; c < 4; c++) acc[a][b][c] = 0.f;

    // preload chunk 0 (phase 0: offsets 0,0)
    uint4 ra0, ra1, rb0, rb1;
    {
        ra0 = *(const uint4*)(Agb + (size_t)r0 * (K2 * 2) + q0 * 16);
        ra1 = *(const uint4*)(Agb + (size_t)r1 * (K2 * 2) + q1 * 16);
        rb0 = *(const uint4*)(Bgb + (size_t)r0 * (K2 * 2) + q0 * 16);
        rb1 = *(const uint4*)(Bgb + (size_t)r1 * (K2 * 2) + q1 * 16);
        *(uint4*)(sAs + r0 * ROWB + q0 * 16) = ra0;
        *(uint4*)(sAs + r1 * ROWB + q1 * 16) = ra1;
        *(uint4*)(sBs + r0 * ROWB + q0 * 16) = rb0;
        *(uint4*)(sBs + r1 * ROWB + q1 * 16) = rb1;
    }
    __syncthreads();

    const uint32_t a_row  = warp_m * 32 + (lane & 15);
    const uint32_t a_colb = (lane >> 4) * 16;
    const uint32_t b_row  = warp_n * 64 + (lane & 7) + ((lane >> 4) & 1) * 8;
    const uint32_t b_colb = ((lane >> 3) & 1) * 16;

#pragma unroll 1
    for (int c = 0; c < NCK; c++) {
        if (c + 1 < NCK) {
            int ao, bo;
            chunk_off(c + 1, ao, bo);
            ra0 = *(const uint4*)(Agb + (size_t)r0 * (K2 * 2) + ao + q0 * 16);
            ra1 = *(const uint4*)(Agb + (size_t)r1 * (K2 * 2) + ao + q1 * 16);
            rb0 = *(const uint4*)(Bgb + (size_t)r0 * (K2 * 2) + bo + q0 * 16);
            rb1 = *(const uint4*)(Bgb + (size_t)r1 * (K2 * 2) + bo + q1 * 16);
        }

#pragma unroll
        for (int ks = 0; ks < 2; ks++) {
            uint32_t afr[2][4], bfr[4][4];
#pragma unroll
            for (int m = 0; m < 2; m++)
                ldm_x4(sA + (a_row + m * 16) * ROWB + ks * 32 + a_colb, afr[m]);
#pragma unroll
            for (int n2 = 0; n2 < 4; n2++)
                ldm_x4(sB + (b_row + n2 * 16) * ROWB + ks * 32 + b_colb, bfr[n2]);
#pragma unroll
            for (int m = 0; m < 2; m++)
#pragma unroll
                for (int nt = 0; nt < 8; nt++)
                    mma16816(acc[m][nt], afr[m], &bfr[nt >> 1][(nt & 1) * 2]);
        }

        __syncthreads();
        if (c + 1 < NCK) {
            *(uint4*)(sAs + r0 * ROWB + q0 * 16) = ra0;
            *(uint4*)(sAs + r1 * ROWB + q1 * 16) = ra1;
            *(uint4*)(sBs + r0 * ROWB + q0 * 16) = rb0;
            *(uint4*)(sBs + r1 * ROWB + q1 * 16) = rb1;
            __syncthreads();
        }
    }

    const int rbase = crow + warp_m * 32 + (lane >> 2);
    const int cbase = tileN + warp_n * 64 + (lane & 3) * 2;
#pragma unroll
    for (int m = 0; m < 2; m++) {
#pragma unroll
        for (int nt = 0; nt < 8; nt++) {
            float* p0 = C + (size_t)(rbase + m * 16)     * Hd + cbase + nt * 8;
            float* p1 = C + (size_t)(rbase + m * 16 + 8) * Hd + cbase + nt * 8;
            *(float2*)p0 = make_float2(acc[m][nt][0], acc[m][nt][1]);
            *(float2*)p1 = make_float2(acc[m][nt][2], acc[m][nt][3]);
        }
    }
}

// ---------------------------------------------------------------------------
// Score kernel: out[b,d,e] = sum_k tanh(enc_t[b,e,k] + dec_t[b,d,k]) * vt[k]
// ---------------------------------------------------------------------------
__global__ __launch_bounds__(256) void score_kernel(
    const float* __restrict__ mask, const float* __restrict__ vt,
    float* __restrict__ out)
{
    extern __shared__ float sm[];
    float* dec_s = sm;
    float* enc_s = sm + 16 * Hd;
    float* vt_s  = sm + 32 * Hd;

    const int b  = blockIdx.z;
    const int dt = blockIdx.y * 16;
    const int et = blockIdx.x * 16;
    const int tid = threadIdx.x;

    const float* decg = g_dec_t + ((size_t)b * DECn + dt) * Hd;
    const float* encg = g_enc_t + ((size_t)b * ENCn + et) * Hd;

    for (int i = tid; i < 16 * Hd / 4; i += 256)
        ((float4*)dec_s)[i] = ((const float4*)decg)[i];
    for (int i = tid; i < 16 * Hd / 4; i += 256)
        ((float4*)enc_s)[i] = ((const float4*)encg)[i];
    for (int i = tid; i < Hd / 4; i += 256)
        ((float4*)vt_s)[i] = ((const float4*)vt)[i];
    __syncthreads();

    const int warp = tid >> 5;
    const int lane = tid & 31;
    const int d0 = 2 * warp;

    float acc[8][4];
#pragma unroll
    for (int ep = 0; ep < 8; ep++)
#pragma unroll
        for (int q = 0; q < 4; q++) acc[ep][q] = 0.f;

    const float* dp0 = dec_s + (size_t)d0 * Hd;
    const float* dp1 = dec_s + (size_t)(d0 + 1) * Hd;

#pragma unroll 1
    for (int c = 0; c < 6; c++) {
        const int k = c * 128 + lane * 4;
        float4 a0 = *(const float4*)(dp0 + k);
        float4 a1 = *(const float4*)(dp1 + k);
        float4 v  = *(const float4*)(vt_s + k);
#pragma unroll
        for (int ep = 0; ep < 8; ep++) {
            float4 b0 = *(const float4*)(enc_s + (size_t)(2 * ep) * Hd + k);
            float4 b1 = *(const float4*)(enc_s + (size_t)(2 * ep + 1) * Hd + k);
            acc[ep][0] = fmaf(tanha(a0.x + b0.x), v.x, acc[ep][0]);
            acc[ep][0] = fmaf(tanha(a0.y + b0.y), v.y, acc[ep][0]);
            acc[ep][0] = fmaf(tanha(a0.z + b0.z), v.z, acc[ep][0]);
            acc[ep][0] = fmaf(tanha(a0.w + b0.w), v.w, acc[ep][0]);
            acc[ep][1] = fmaf(tanha(a0.x + b1.x), v.x, acc[ep][1]);
            acc[ep][1] = fmaf(tanha(a0.y + b1.y), v.y, acc[ep][1]);
            acc[ep][1] = fmaf(tanha(a0.z + b1.z), v.z, acc[ep][1]);
            acc[ep][1] = fmaf(tanha(a0.w + b1.w), v.w, acc[ep][1]);
            acc[ep][2] = fmaf(tanha(a1.x + b0.x), v.x, acc[ep][2]);
            acc[ep][2] = fmaf(tanha(a1.y + b0.y), v.y, acc[ep][2]);
            acc[ep][2] = fmaf(tanha(a1.z + b0.z), v.z, acc[ep][2]);
            acc[ep][2] = fmaf(tanha(a1.w + b0.w), v.w, acc[ep][2]);
            acc[ep][3] = fmaf(tanha(a1.x + b1.x), v.x, acc[ep][3]);
            acc[ep][3] = fmaf(tanha(a1.y + b1.y), v.y, acc[ep][3]);
            acc[ep][3] = fmaf(tanha(a1.z + b1.z), v.z, acc[ep][3]);
            acc[ep][3] = fmaf(tanha(a1.w + b1.w), v.w, acc[ep][3]);
        }
    }

#pragma unroll
    for (int ep = 0; ep < 8; ep++)
#pragma unroll
        for (int q = 0; q < 4; q++) {
#pragma unroll
            for (int off = 16; off > 0; off >>= 1)
                acc[ep][q] += __shfl_xor_sync(0xFFFFFFFFu, acc[ep][q], off);
        }

    if (lane == 0) {
        const size_t half = (size_t)Bn * DECn * ENCn;
#pragma unroll
        for (int ep = 0; ep < 8; ep++) {
#pragma unroll
            for (int q = 0; q < 4; q++) {
                const int di = q >> 1;
                const int ei = q & 1;
                const int d = dt + d0 + di;
                const int e = et + 2 * ep + ei;
                const size_t idx = ((size_t)b * DECn + d) * ENCn + e;
                const float raw = acc[ep][q];
                out[idx]        = raw + mask[idx];
                out[half + idx] = raw;
            }
        }
    }
}

// ---------------------------------------------------------------------------
extern "C" void kernel_launch(void* const* d_in, const int* in_sizes, int n_in,
                              void* d_out, int out_size)
{
    const float* dec  = (const float*)d_in[0];
    const float* enc  = (const float*)d_in[1];
    const float* mask = (const float*)d_in[2];
    const float* W1   = (const float*)d_in[3];
    const float* W2   = (const float*)d_in[4];
    const float* vt   = (const float*)d_in[5];
    float* out = (float*)d_out;

    float *enc_t_p, *dec_t_p;
    __nv_bfloat16 *insp_p, *w1t_p, *w2t_p;
    cudaGetSymbolAddress((void**)&enc_t_p, g_enc_t);
    cudaGetSymbolAddress((void**)&dec_t_p, g_dec_t);
    cudaGetSymbolAddress((void**)&insp_p, g_in_split);
    cudaGetSymbolAddress((void**)&w1t_p, g_w1t);
    cudaGetSymbolAddress((void**)&w2t_p, g_w2t);

    split_kernel<<<(Bn * ENCn * (Hd / 4) + 255) / 256, 256>>>(enc, insp_p, Bn * ENCn);
    split_kernel<<<(Bn * DECn * (Hd / 4) + 255) / 256, 256>>>(
        dec, insp_p + (size_t)(Bn * ENCn) * K2, Bn * DECn);
    wsplit_kernel<<<dim3(Hd / 32, Hd / 32), dim3(32, 8)>>>(W1, w1t_p);
    wsplit_kernel<<<dim3(Hd / 32, Hd / 32), dim3(32, 8)>>>(W2, w2t_p);

    gemm_tc_mma<<<dim3(Hd / 128, MROWS / 128), 256>>>(
        insp_p, w1t_p, w2t_p, enc_t_p, dec_t_p);

    const int smem_bytes = (32 * Hd + Hd) * sizeof(float);
    cudaFuncSetAttribute(score_kernel, cudaFuncAttributeMaxDynamicSharedMemorySize, smem_bytes);
    score_kernel<<<dim3(ENCn / 16, DECn / 16, Bn), 256, smem_bytes>>>(mask, vt, out);
}

// round 5
// speedup vs baseline: 1.5723x; 1.0167x over previous
#include <cuda_runtime.h>
#include <cuda_bf16.h>
#include <cstdint>

#define Hd   768
#define Bn   4
#define DECn 128
#define ENCn 512
#define K2   1536          // stored split K (hi | lo)
#define MROWS (Bn*ENCn + Bn*DECn)   // 2560
#define NTILES 1024        // 4 b * 8 dec-tiles * 32 enc-tiles

// ---------------- scratch (__device__ globals; no allocs allowed) ----------
__device__ float          g_enc_t[Bn * ENCn * Hd];
__device__ float          g_dec_t[Bn * DECn * Hd];
__device__ __nv_bfloat16  g_in_split[MROWS * K2];
__device__ __nv_bfloat16  g_w1t[Hd * K2];   // W1^T split: [n][hi(768)|lo(768)]
__device__ __nv_bfloat16  g_w2t[Hd * K2];   // W2^T split

__device__ __forceinline__ float tanha(float x) {
    float y;
    asm("tanh.approx.f32 %0, %1;" : "=f"(y) : "f"(x));
    return y;
}
__device__ __forceinline__ uint32_t smem_u32(const void* p) {
    return (uint32_t)__cvta_generic_to_shared(p);
}
__device__ __forceinline__ void ldm_x4(uint32_t addr, uint32_t* r) {
    asm volatile("ldmatrix.sync.aligned.m8n8.x4.shared.b16 {%0,%1,%2,%3}, [%4];"
        : "=r"(r[0]), "=r"(r[1]), "=r"(r[2]), "=r"(r[3]) : "r"(addr));
}
__device__ __forceinline__ void mma16816(float* d, const uint32_t* a, const uint32_t* b) {
    asm volatile("mma.sync.aligned.m16n8k16.row.col.f32.bf16.bf16.f32 "
        "{%0,%1,%2,%3}, {%4,%5,%6,%7}, {%8,%9}, {%0,%1,%2,%3};"
        : "+f"(d[0]), "+f"(d[1]), "+f"(d[2]), "+f"(d[3])
        : "r"(a[0]), "r"(a[1]), "r"(a[2]), "r"(a[3]), "r"(b[0]), "r"(b[1]));
}
#define CP_ASYNC16(saddr, gptr) \
    asm volatile("cp.async.cg.shared.global [%0], [%1], 16;" :: "r"(saddr), "l"(gptr))
#define CP_COMMIT() asm volatile("cp.async.commit_group;" ::: "memory")
#define CP_WAIT(n)  asm volatile("cp.async.wait_group %0;" :: "n"(n) : "memory")

// ---------------------------------------------------------------------------
// fp32 -> bf16 hi|lo split for enc (rows 0..2047) and dec (rows 2048..2559)
// ---------------------------------------------------------------------------
__global__ __launch_bounds__(256) void split_all(
    const float* __restrict__ enc, const float* __restrict__ dec,
    __nv_bfloat16* __restrict__ dst)
{
    int i = blockIdx.x * 256 + threadIdx.x;      // one float4 group
    if (i >= MROWS * (Hd / 4)) return;
    int row = i / (Hd / 4);
    int c4  = (i % (Hd / 4)) * 4;
    const float* src = (row < Bn * ENCn)
        ? enc + (size_t)row * Hd + c4
        : dec + (size_t)(row - Bn * ENCn) * Hd + c4;
    float4 v = *(const float4*)src;
    __nv_bfloat16 h0 = __float2bfloat16(v.x), h1 = __float2bfloat16(v.y);
    __nv_bfloat16 h2 = __float2bfloat16(v.z), h3 = __float2bfloat16(v.w);
    float l0 = v.x - __bfloat162float(h0), l1 = v.y - __bfloat162float(h1);
    float l2 = v.z - __bfloat162float(h2), l3 = v.w - __bfloat162float(h3);
    __nv_bfloat16* dh = dst + (size_t)row * K2 + c4;
    __nv_bfloat16* dl = dh + Hd;
    *(__nv_bfloat162*)(dh)     = __nv_bfloat162(h0, h1);
    *(__nv_bfloat162*)(dh + 2) = __nv_bfloat162(h2, h3);
    *(__nv_bfloat162*)(dl)     = __floats2bfloat162_rn(l0, l1);
    *(__nv_bfloat162*)(dl + 2) = __floats2bfloat162_rn(l2, l3);
}

// W1/W2 (768 k x 768 n) -> transposed split dst[n][hi|lo]; z selects matrix
__global__ __launch_bounds__(256) void wsplit_all(
    const float* __restrict__ W1, const float* __restrict__ W2,
    __nv_bfloat16* __restrict__ D1, __nv_bfloat16* __restrict__ D2)
{
    __shared__ float t[32][33];
    const float* W = blockIdx.z ? W2 : W1;
    __nv_bfloat16* dst = blockIdx.z ? D2 : D1;
    int k0 = blockIdx.y * 32, n0 = blockIdx.x * 32;
    int tx = threadIdx.x, ty = threadIdx.y;   // 32 x 8
#pragma unroll
    for (int j = 0; j < 4; j++)
        t[ty + j * 8][tx] = W[(size_t)(k0 + ty + j * 8) * Hd + n0 + tx];
    __syncthreads();
#pragma unroll
    for (int j = 0; j < 4; j++) {
        int n = n0 + ty + j * 8;
        int k = k0 + tx;
        float x = t[tx][ty + j * 8];
        __nv_bfloat16 h = __float2bfloat16(x);
        float l = x - __bfloat162float(h);
        dst[(size_t)n * K2 + k]      = h;
        dst[(size_t)n * K2 + Hd + k] = __float2bfloat16(l);
    }
}

// ---------------------------------------------------------------------------
// Tensor-core GEMM, 3-term bf16 split: C = ah*bh + al*bh + ah*bl
// 72 K-chunks of 32; cp.async 2-stage pipeline; tile 128x128, 8 warps.
// ---------------------------------------------------------------------------
#define BK   32
#define ROWB 80
#define NCK  72
#define BUFB (128 * ROWB)

__device__ __forceinline__ void chunk_off(int c, int& ao, int& bo) {
    const int phase = c / 24;
    const int r     = c - phase * 24;
    const int base  = r * (BK * 2);
    ao = base + (phase == 1 ? Hd * 2 : 0);
    bo = base + (phase == 2 ? Hd * 2 : 0);
}

__global__ __launch_bounds__(256, 1)
void gemm_tc_mma(const __nv_bfloat16* __restrict__ Asp,
                 const __nv_bfloat16* __restrict__ W1sp,
                 const __nv_bfloat16* __restrict__ W2sp,
                 float* __restrict__ Cenc, float* __restrict__ Cdec)
{
    __shared__ __align__(16) char sAs[2 * BUFB];
    __shared__ __align__(16) char sBs[2 * BUFB];

    const int tid    = threadIdx.x;
    const int wid    = tid >> 5;
    const int lane   = tid & 31;
    const int warp_m = wid & 3;
    const int warp_n = wid >> 2;

    const int tileN = blockIdx.x * 128;
    const int mt    = blockIdx.y * 128;
    const __nv_bfloat16* Bsp;
    float* C; int crow;
    if (mt < Bn * ENCn) { Bsp = W1sp; C = Cenc; crow = mt; }
    else                { Bsp = W2sp; C = Cdec; crow = mt - Bn * ENCn; }

    const char* Agb = (const char*)(Asp + (size_t)mt   * K2);
    const char* Bgb = (const char*)(Bsp + (size_t)tileN * K2);

    const uint32_t sA = smem_u32(sAs);
    const uint32_t sB = smem_u32(sBs);

    // per-thread copy mapping: 512 16B segs per matrix per chunk, 2 per thread
    const int rA0 = tid >> 2,        qA0 = (tid & 3) * 16;
    const int rA1 = (tid + 256) >> 2, qA1 = (tid & 3) * 16;

    float acc[2][8][4];
#pragma unroll
    for (int a = 0; a < 2; a++)
#pragma unroll
        for (int b = 0; b < 8; b++)
#pragma unroll
            for (int c = 0; c < 4; c++) acc[a][b][c] = 0.f;

    // prologue: issue chunks 0 and 1
#pragma unroll
    for (int c0 = 0; c0 < 2; c0++) {
        int ao, bo; chunk_off(c0, ao, bo);
        uint32_t da = sA + c0 * BUFB, db = sB + c0 * BUFB;
        CP_ASYNC16(da + rA0 * ROWB + qA0, Agb + (size_t)rA0 * (K2 * 2) + ao + qA0);
        CP_ASYNC16(da + rA1 * ROWB + qA1, Agb + (size_t)rA1 * (K2 * 2) + ao + qA1);
        CP_ASYNC16(db + rA0 * ROWB + qA0, Bgb + (size_t)rA0 * (K2 * 2) + bo + qA0);
        CP_ASYNC16(db + rA1 * ROWB + qA1, Bgb + (size_t)rA1 * (K2 * 2) + bo + qA1);
        CP_COMMIT();
    }

    const uint32_t a_row  = warp_m * 32 + (lane & 15);
    const uint32_t a_colb = (lane >> 4) * 16;
    const uint32_t b_row  = warp_n * 64 + (lane & 7) + ((lane >> 4) & 1) * 8;
    const uint32_t b_colb = ((lane >> 3) & 1) * 16;

#pragma unroll 1
    for (int c = 0; c < NCK; c++) {
        const int buf = c & 1;
        if (c + 1 < NCK) CP_WAIT(1); else CP_WAIT(0);
        __syncthreads();

        const uint32_t bA = sA + buf * BUFB;
        const uint32_t bB = sB + buf * BUFB;
#pragma unroll
        for (int ks = 0; ks < 2; ks++) {
            uint32_t afr[2][4], bfr[4][4];
#pragma unroll
            for (int m = 0; m < 2; m++)
                ldm_x4(bA + (a_row + m * 16) * ROWB + ks * 32 + a_colb, afr[m]);
#pragma unroll
            for (int n2 = 0; n2 < 4; n2++)
                ldm_x4(bB + (b_row + n2 * 16) * ROWB + ks * 32 + b_colb, bfr[n2]);
#pragma unroll
            for (int m = 0; m < 2; m++)
#pragma unroll
                for (int nt = 0; nt < 8; nt++)
                    mma16816(acc[m][nt], afr[m], &bfr[nt >> 1][(nt & 1) * 2]);
        }
        __syncthreads();

        if (c + 2 < NCK) {
            int ao, bo; chunk_off(c + 2, ao, bo);
            uint32_t da = sA + buf * BUFB, db = sB + buf * BUFB;
            CP_ASYNC16(da + rA0 * ROWB + qA0, Agb + (size_t)rA0 * (K2 * 2) + ao + qA0);
            CP_ASYNC16(da + rA1 * ROWB + qA1, Agb + (size_t)rA1 * (K2 * 2) + ao + qA1);
            CP_ASYNC16(db + rA0 * ROWB + qA0, Bgb + (size_t)rA0 * (K2 * 2) + bo + qA0);
            CP_ASYNC16(db + rA1 * ROWB + qA1, Bgb + (size_t)rA1 * (K2 * 2) + bo + qA1);
            CP_COMMIT();
        }
    }

    const int rbase = crow + warp_m * 32 + (lane >> 2);
    const int cbase = tileN + warp_n * 64 + (lane & 3) * 2;
#pragma unroll
    for (int m = 0; m < 2; m++) {
#pragma unroll
        for (int nt = 0; nt < 8; nt++) {
            float* p0 = C + (size_t)(rbase + m * 16)     * Hd + cbase + nt * 8;
            float* p1 = C + (size_t)(rbase + m * 16 + 8) * Hd + cbase + nt * 8;
            *(float2*)p0 = make_float2(acc[m][nt][0], acc[m][nt][1]);
            *(float2*)p1 = make_float2(acc[m][nt][2], acc[m][nt][3]);
        }
    }
}

// ---------------------------------------------------------------------------
// Persistent score kernel: out[b,d,e] = sum_k tanh(enc_t[b,e,k]+dec_t[b,d,k])*vt[k]
// grid = #SMs, 512 threads (16 warps). Warp w owns dec row dt+w (in registers).
// vt in registers. Only enc tiles (16x768) in smem, double-buffered cp.async.
// Tile t: strip = t>>5 (b = strip>>3, dt=(strip&7)*16), et = (t&31)*16.
// ---------------------------------------------------------------------------
#define SC_TILEF (16 * Hd)           // floats per enc tile (12288)
#define SC_SMEM  (2 * SC_TILEF * 4)  // 98304 bytes

__global__ __launch_bounds__(512, 1) void score_kernel(
    const float* __restrict__ enc_t, const float* __restrict__ dec_t,
    const float* __restrict__ mask,  const float* __restrict__ vt,
    float* __restrict__ out)
{
    extern __shared__ float es[];    // 2 x 12288 floats
    const int tid  = threadIdx.x;
    const int wid  = tid >> 5;
    const int lane = tid & 31;
    const int G    = gridDim.x;
    const int ts   = (int)(((long long)blockIdx.x       * NTILES) / G);
    const int te   = (int)(((long long)(blockIdx.x + 1) * NTILES) / G);
    if (ts >= te) return;

    // vt in registers
    float4 vreg[6];
#pragma unroll
    for (int c = 0; c < 6; c++)
        vreg[c] = *(const float4*)(vt + c * 128 + lane * 4);

    float4 areg[6];
    int cur_strip = -1;
    const uint32_t es_s = smem_u32(es);

    // prologue: cp.async enc tile ts -> buf 0
    {
        int t0 = ts;
        int b = (t0 >> 5) >> 3, et = (t0 & 31) << 4;
        const float* src = enc_t + ((size_t)b * ENCn + et) * Hd;
#pragma unroll
        for (int i = 0; i < 6; i++) {
            int seg = i * 512 + tid;                 // 0..3071
            CP_ASYNC16(es_s + seg * 16, src + seg * 4);
        }
        CP_COMMIT();
    }

#pragma unroll 1
    for (int t = ts; t < te; t++) {
        const int buf   = (t - ts) & 1;
        const int strip = t >> 5;
        const int b     = strip >> 3;
        const int dt    = (strip & 7) << 4;
        const int et    = (t & 31) << 4;

        // prefetch next enc tile into the other buffer
        if (t + 1 < te) {
            int b2 = ((t + 1) >> 5) >> 3, et2 = ((t + 1) & 31) << 4;
            const float* src = enc_t + ((size_t)b2 * ENCn + et2) * Hd;
            uint32_t dst = es_s + (buf ^ 1) * (SC_TILEF * 4);
#pragma unroll
            for (int i = 0; i < 6; i++) {
                int seg = i * 512 + tid;
                CP_ASYNC16(dst + seg * 16, src + seg * 4);
            }
            CP_COMMIT();
            CP_WAIT(1);          // tile t resident, t+1 in flight
        } else {
            CP_WAIT(0);
        }
        __syncthreads();

        // dec row in registers (reload only when strip changes)
        if (strip != cur_strip) {
            cur_strip = strip;
            const float* dp = dec_t + ((size_t)(b * DECn + dt + wid)) * Hd;
#pragma unroll
            for (int c = 0; c < 6; c++)
                areg[c] = *(const float4*)(dp + c * 128 + lane * 4);
        }

        const float* eb = es + buf * SC_TILEF;
        float acc[16];
#pragma unroll
        for (int e = 0; e < 16; e++) acc[e] = 0.f;

#pragma unroll
        for (int c = 0; c < 6; c++) {
            const float4 a = areg[c];
            const float4 v = vreg[c];
            const int k = c * 128 + lane * 4;
#pragma unroll
            for (int e = 0; e < 16; e++) {
                float4 bb = *(const float4*)(eb + e * Hd + k);
                acc[e] = fmaf(tanha(a.x + bb.x), v.x, acc[e]);
                acc[e] = fmaf(tanha(a.y + bb.y), v.y, acc[e]);
                acc[e] = fmaf(tanha(a.z + bb.z), v.z, acc[e]);
                acc[e] = fmaf(tanha(a.w + bb.w), v.w, acc[e]);
            }
        }
        __syncthreads();   // all warps done reading buf before it is overwritten

        // reduce across lanes
#pragma unroll
        for (int e = 0; e < 16; e++) {
#pragma unroll
            for (int off = 16; off > 0; off >>= 1)
                acc[e] += __shfl_xor_sync(0xFFFFFFFFu, acc[e], off);
        }

        if (lane == 0) {
            const size_t half = (size_t)Bn * DECn * ENCn;
            const size_t idx0 = ((size_t)(b * DECn + dt + wid)) * ENCn + et;
#pragma unroll
            for (int q = 0; q < 4; q++) {
                float4 m = *(const float4*)(mask + idx0 + q * 4);
                float4 r = make_float4(acc[q*4], acc[q*4+1], acc[q*4+2], acc[q*4+3]);
                *(float4*)(out + idx0 + q * 4) =
                    make_float4(r.x + m.x, r.y + m.y, r.z + m.z, r.w + m.w);
                *(float4*)(out + half + idx0 + q * 4) = r;
            }
        }
    }
}

// ---------------------------------------------------------------------------
extern "C" void kernel_launch(void* const* d_in, const int* in_sizes, int n_in,
                              void* d_out, int out_size)
{
    const float* dec  = (const float*)d_in[0];
    const float* enc  = (const float*)d_in[1];
    const float* mask = (const float*)d_in[2];
    const float* W1   = (const float*)d_in[3];
    const float* W2   = (const float*)d_in[4];
    const float* vt   = (const float*)d_in[5];
    float* out = (float*)d_out;

    float *enc_t_p, *dec_t_p;
    __nv_bfloat16 *insp_p, *w1t_p, *w2t_p;
    cudaGetSymbolAddress((void**)&enc_t_p, g_enc_t);
    cudaGetSymbolAddress((void**)&dec_t_p, g_dec_t);
    cudaGetSymbolAddress((void**)&insp_p, g_in_split);
    cudaGetSymbolAddress((void**)&w1t_p, g_w1t);
    cudaGetSymbolAddress((void**)&w2t_p, g_w2t);

    int nsm = 148;
    cudaDeviceGetAttribute(&nsm, cudaDevAttrMultiProcessorCount, 0);

    split_all<<<(MROWS * (Hd / 4) + 255) / 256, 256>>>(enc, dec, insp_p);
    wsplit_all<<<dim3(Hd / 32, Hd / 32, 2), dim3(32, 8)>>>(W1, W2, w1t_p, w2t_p);

    gemm_tc_mma<<<dim3(Hd / 128, MROWS / 128), 256>>>(
        insp_p, w1t_p, w2t_p, enc_t_p, dec_t_p);

    cudaFuncSetAttribute(score_kernel, cudaFuncAttributeMaxDynamicSharedMemorySize, SC_SMEM);
    score_kernel<<<nsm, 512, SC_SMEM>>>(enc_t_p, dec_t_p, mask, vt, out);
}

// round 6
// speedup vs baseline: 1.7358x; 1.1040x over previous
#include <cuda_runtime.h>
#include <cuda_bf16.h>
#include <cstdint>

#define Hd   768
#define Bn   4
#define DECn 128
#define ENCn 512
#define K2   1536          // stored split K (hi | lo)
#define MROWS (Bn*ENCn + Bn*DECn)   // 2560
#define NTILES 1024        // 4 b * 8 dec-tiles * 32 enc-tiles

// ---------------- scratch (__device__ globals; no allocs allowed) ----------
__device__ float          g_enc_t[Bn * ENCn * Hd];
__device__ float          g_dec_t[Bn * DECn * Hd];
__device__ __nv_bfloat16  g_in_split[MROWS * K2];
__device__ __nv_bfloat16  g_w1t[Hd * K2];   // W1^T split: [n][hi(768)|lo(768)]
__device__ __nv_bfloat16  g_w2t[Hd * K2];   // W2^T split

__device__ __forceinline__ float tanha(float x) {
    float y;
    asm("tanh.approx.f32 %0, %1;" : "=f"(y) : "f"(x));
    return y;
}
__device__ __forceinline__ uint32_t smem_u32(const void* p) {
    return (uint32_t)__cvta_generic_to_shared(p);
}
__device__ __forceinline__ void ldm_x4(uint32_t addr, uint32_t* r) {
    asm volatile("ldmatrix.sync.aligned.m8n8.x4.shared.b16 {%0,%1,%2,%3}, [%4];"
        : "=r"(r[0]), "=r"(r[1]), "=r"(r[2]), "=r"(r[3]) : "r"(addr));
}
__device__ __forceinline__ void mma16816(float* d, const uint32_t* a, const uint32_t* b) {
    asm volatile("mma.sync.aligned.m16n8k16.row.col.f32.bf16.bf16.f32 "
        "{%0,%1,%2,%3}, {%4,%5,%6,%7}, {%8,%9}, {%0,%1,%2,%3};"
        : "+f"(d[0]), "+f"(d[1]), "+f"(d[2]), "+f"(d[3])
        : "r"(a[0]), "r"(a[1]), "r"(a[2]), "r"(a[3]), "r"(b[0]), "r"(b[1]));
}
#define CP_ASYNC16(saddr, gptr) \
    asm volatile("cp.async.cg.shared.global [%0], [%1], 16;" :: "r"(saddr), "l"(gptr))
#define CP_COMMIT() asm volatile("cp.async.commit_group;" ::: "memory")
#define CP_WAIT(n)  asm volatile("cp.async.wait_group %0;" :: "n"(n) : "memory")

// ---------------------------------------------------------------------------
// prep: blocks [0, NB_SPLIT) do input hi|lo split; rest do W transpose+split.
// ---------------------------------------------------------------------------
#define NB_SPLIT (MROWS * (Hd / 4) / 256)          // 1920
#define NB_WT    ((Hd / 32) * (Hd / 32))           // 576 per matrix

__global__ __launch_bounds__(256) void prep_kernel(
    const float* __restrict__ enc, const float* __restrict__ dec,
    const float* __restrict__ W1,  const float* __restrict__ W2,
    __nv_bfloat16* __restrict__ dst,
    __nv_bfloat16* __restrict__ D1, __nv_bfloat16* __restrict__ D2)
{
    const int bid = blockIdx.x;
    const int tid = threadIdx.x;
    if (bid < NB_SPLIT) {
        int i = bid * 256 + tid;
        int row = i / (Hd / 4);
        int c4  = (i % (Hd / 4)) * 4;
        const float* src = (row < Bn * ENCn)
            ? enc + (size_t)row * Hd + c4
            : dec + (size_t)(row - Bn * ENCn) * Hd + c4;
        float4 v = *(const float4*)src;
        __nv_bfloat16 h0 = __float2bfloat16(v.x), h1 = __float2bfloat16(v.y);
        __nv_bfloat16 h2 = __float2bfloat16(v.z), h3 = __float2bfloat16(v.w);
        float l0 = v.x - __bfloat162float(h0), l1 = v.y - __bfloat162float(h1);
        float l2 = v.z - __bfloat162float(h2), l3 = v.w - __bfloat162float(h3);
        __nv_bfloat16* dh = dst + (size_t)row * K2 + c4;
        __nv_bfloat16* dl = dh + Hd;
        *(__nv_bfloat162*)(dh)     = __nv_bfloat162(h0, h1);
        *(__nv_bfloat162*)(dh + 2) = __nv_bfloat162(h2, h3);
        *(__nv_bfloat162*)(dl)     = __floats2bfloat162_rn(l0, l1);
        *(__nv_bfloat162*)(dl + 2) = __floats2bfloat162_rn(l2, l3);
    } else {
        __shared__ float t[32][33];
        const int b2  = bid - NB_SPLIT;
        const int z   = b2 / NB_WT;
        const int rem = b2 - z * NB_WT;
        const int bx  = rem % (Hd / 32);
        const int by  = rem / (Hd / 32);
        const float* W = z ? W2 : W1;
        __nv_bfloat16* d = z ? D2 : D1;
        const int k0 = by * 32, n0 = bx * 32;
        const int tx = tid & 31, ty = tid >> 5;   // 32 x 8
#pragma unroll
        for (int j = 0; j < 4; j++)
            t[ty + j * 8][tx] = W[(size_t)(k0 + ty + j * 8) * Hd + n0 + tx];
        __syncthreads();
#pragma unroll
        for (int j = 0; j < 4; j++) {
            int n = n0 + ty + j * 8;
            int k = k0 + tx;
            float x = t[tx][ty + j * 8];
            __nv_bfloat16 h = __float2bfloat16(x);
            float l = x - __bfloat162float(h);
            d[(size_t)n * K2 + k]      = h;
            d[(size_t)n * K2 + Hd + k] = __float2bfloat16(l);
        }
    }
}

// ---------------------------------------------------------------------------
// Tensor-core GEMM, 3-term bf16 split: C = ah*bh + al*bh + ah*bl
// 72 K-chunks of 32; 4-stage cp.async ring, ONE __syncthreads per chunk.
// Tile 128x128, 8 warps (4m x 2n), warp tile 32x64; 80B-padded SMEM rows.
// ---------------------------------------------------------------------------
#define BK     32
#define ROWB   80
#define NCK    72
#define BUFB   (128 * ROWB)
#define STAGES 4
#define GEMM_SMEM (2 * STAGES * BUFB)   // 81920

__device__ __forceinline__ void chunk_off(int c, int& ao, int& bo) {
    const int phase = c / 24;
    const int r     = c - phase * 24;
    const int base  = r * (BK * 2);
    ao = base + (phase == 1 ? Hd * 2 : 0);
    bo = base + (phase == 2 ? Hd * 2 : 0);
}

__global__ __launch_bounds__(256, 1)
void gemm_tc_mma(const __nv_bfloat16* __restrict__ Asp,
                 const __nv_bfloat16* __restrict__ W1sp,
                 const __nv_bfloat16* __restrict__ W2sp,
                 float* __restrict__ Cenc, float* __restrict__ Cdec)
{
    extern __shared__ __align__(16) char gsm[];
    const uint32_t sA = smem_u32(gsm);                    // STAGES bufs A
    const uint32_t sB = sA + STAGES * BUFB;               // STAGES bufs B

    const int tid    = threadIdx.x;
    const int wid    = tid >> 5;
    const int lane   = tid & 31;
    const int warp_m = wid & 3;
    const int warp_n = wid >> 2;

    const int tileN = blockIdx.x * 128;
    const int mt    = blockIdx.y * 128;
    const __nv_bfloat16* Bsp;
    float* C; int crow;
    if (mt < Bn * ENCn) { Bsp = W1sp; C = Cenc; crow = mt; }
    else                { Bsp = W2sp; C = Cdec; crow = mt - Bn * ENCn; }

    const char* Agb = (const char*)(Asp + (size_t)mt   * K2);
    const char* Bgb = (const char*)(Bsp + (size_t)tileN * K2);

    // per-thread copy mapping: 512 16B segs per matrix per chunk, 2 per thread
    const int rA0 = tid >> 2,         qA0 = (tid & 3) * 16;
    const int rA1 = (tid + 256) >> 2, qA1 = (tid & 3) * 16;

    float acc[2][8][4];
#pragma unroll
    for (int a = 0; a < 2; a++)
#pragma unroll
        for (int b = 0; b < 8; b++)
#pragma unroll
            for (int c = 0; c < 4; c++) acc[a][b][c] = 0.f;

    // prologue: issue chunks 0..2 (groups 0..2)
#pragma unroll
    for (int c0 = 0; c0 < 3; c0++) {
        int ao, bo; chunk_off(c0, ao, bo);
        uint32_t da = sA + c0 * BUFB, db = sB + c0 * BUFB;
        CP_ASYNC16(da + rA0 * ROWB + qA0, Agb + (size_t)rA0 * (K2 * 2) + ao + qA0);
        CP_ASYNC16(da + rA1 * ROWB + qA1, Agb + (size_t)rA1 * (K2 * 2) + ao + qA1);
        CP_ASYNC16(db + rA0 * ROWB + qA0, Bgb + (size_t)rA0 * (K2 * 2) + bo + qA0);
        CP_ASYNC16(db + rA1 * ROWB + qA1, Bgb + (size_t)rA1 * (K2 * 2) + bo + qA1);
        CP_COMMIT();
    }

    const uint32_t a_row  = warp_m * 32 + (lane & 15);
    const uint32_t a_colb = (lane >> 4) * 16;
    const uint32_t b_row  = warp_n * 64 + (lane & 7) + ((lane >> 4) & 1) * 8;
    const uint32_t b_colb = ((lane >> 3) & 1) * 16;

#pragma unroll 1
    for (int c = 0; c < NCK; c++) {
        const int buf = c & (STAGES - 1);
        CP_WAIT(2);              // group for chunk c complete (c+1, c+2 pending)
        __syncthreads();         // also guards reuse of buf (c+3)&3 == (c-1)&3

        // issue chunk c+3 (empty group if past end -> keeps wait accounting)
        if (c + 3 < NCK) {
            int ao, bo; chunk_off(c + 3, ao, bo);
            const int nb = (c + 3) & (STAGES - 1);
            uint32_t da = sA + nb * BUFB, db = sB + nb * BUFB;
            CP_ASYNC16(da + rA0 * ROWB + qA0, Agb + (size_t)rA0 * (K2 * 2) + ao + qA0);
            CP_ASYNC16(da + rA1 * ROWB + qA1, Agb + (size_t)rA1 * (K2 * 2) + ao + qA1);
            CP_ASYNC16(db + rA0 * ROWB + qA0, Bgb + (size_t)rA0 * (K2 * 2) + bo + qA0);
            CP_ASYNC16(db + rA1 * ROWB + qA1, Bgb + (size_t)rA1 * (K2 * 2) + bo + qA1);
        }
        CP_COMMIT();

        const uint32_t bA = sA + buf * BUFB;
        const uint32_t bB = sB + buf * BUFB;
#pragma unroll
        for (int ks = 0; ks < 2; ks++) {
            uint32_t afr[2][4], bfr[4][4];
#pragma unroll
            for (int m = 0; m < 2; m++)
                ldm_x4(bA + (a_row + m * 16) * ROWB + ks * 32 + a_colb, afr[m]);
#pragma unroll
            for (int n2 = 0; n2 < 4; n2++)
                ldm_x4(bB + (b_row + n2 * 16) * ROWB + ks * 32 + b_colb, bfr[n2]);
#pragma unroll
            for (int m = 0; m < 2; m++)
#pragma unroll
                for (int nt = 0; nt < 8; nt++)
                    mma16816(acc[m][nt], afr[m], &bfr[nt >> 1][(nt & 1) * 2]);
        }
    }

    const int rbase = crow + warp_m * 32 + (lane >> 2);
    const int cbase = tileN + warp_n * 64 + (lane & 3) * 2;
#pragma unroll
    for (int m = 0; m < 2; m++) {
#pragma unroll
        for (int nt = 0; nt < 8; nt++) {
            float* p0 = C + (size_t)(rbase + m * 16)     * Hd + cbase + nt * 8;
            float* p1 = C + (size_t)(rbase + m * 16 + 8) * Hd + cbase + nt * 8;
            *(float2*)p0 = make_float2(acc[m][nt][0], acc[m][nt][1]);
            *(float2*)p1 = make_float2(acc[m][nt][2], acc[m][nt][3]);
        }
    }
}

// ---------------------------------------------------------------------------
// Persistent score kernel, ONE __syncthreads per tile.
// grid = #SMs, 512 threads (16 warps). Warp w owns dec row dt+w (registers).
// vt in registers. enc tiles (16x768) double-buffered via cp.async.
// ---------------------------------------------------------------------------
#define SC_TILEF (16 * Hd)           // floats per enc tile (12288)
#define SC_SMEM  (2 * SC_TILEF * 4)  // 98304 bytes

__global__ __launch_bounds__(512, 1) void score_kernel(
    const float* __restrict__ enc_t, const float* __restrict__ dec_t,
    const float* __restrict__ mask,  const float* __restrict__ vt,
    float* __restrict__ out)
{
    extern __shared__ float es[];
    const int tid  = threadIdx.x;
    const int wid  = tid >> 5;
    const int lane = tid & 31;
    const int G    = gridDim.x;
    const int ts   = (int)(((long long)blockIdx.x       * NTILES) / G);
    const int te   = (int)(((long long)(blockIdx.x + 1) * NTILES) / G);
    if (ts >= te) return;

    float4 vreg[6];
#pragma unroll
    for (int c = 0; c < 6; c++)
        vreg[c] = *(const float4*)(vt + c * 128 + lane * 4);

    float4 areg[6];
    int cur_strip = -1;
    const uint32_t es_s = smem_u32(es);

    // prologue: issue enc tile ts -> buf 0
    {
        int b = (ts >> 5) >> 3, et = (ts & 31) << 4;
        const float* src = enc_t + ((size_t)b * ENCn + et) * Hd;
#pragma unroll
        for (int i = 0; i < 6; i++) {
            int seg = i * 512 + tid;
            CP_ASYNC16(es_s + seg * 16, src + seg * 4);
        }
        CP_COMMIT();
    }

#pragma unroll 1
    for (int t = ts; t < te; t++) {
        const int buf   = (t - ts) & 1;
        const int strip = t >> 5;
        const int b     = strip >> 3;
        const int dt    = (strip & 7) << 4;
        const int et    = (t & 31) << 4;

        CP_WAIT(0);          // tile t resident (only group pending)
        __syncthreads();     // all warps done with buf^1 (tile t-1) -> safe overwrite

        // prefetch t+1 into buf^1, overlapped with compute of t
        if (t + 1 < te) {
            int b2 = ((t + 1) >> 5) >> 3, et2 = ((t + 1) & 31) << 4;
            const float* src = enc_t + ((size_t)b2 * ENCn + et2) * Hd;
            uint32_t dst = es_s + (buf ^ 1) * (SC_TILEF * 4);
#pragma unroll
            for (int i = 0; i < 6; i++) {
                int seg = i * 512 + tid;
                CP_ASYNC16(dst + seg * 16, src + seg * 4);
            }
            CP_COMMIT();
        }

        if (strip != cur_strip) {
            cur_strip = strip;
            const float* dp = dec_t + ((size_t)(b * DECn + dt + wid)) * Hd;
#pragma unroll
            for (int c = 0; c < 6; c++)
                areg[c] = *(const float4*)(dp + c * 128 + lane * 4);
        }

        const float* eb = es + buf * SC_TILEF;
        float acc[16];
#pragma unroll
        for (int e = 0; e < 16; e++) acc[e] = 0.f;

#pragma unroll
        for (int c = 0; c < 6; c++) {
            const float4 a = areg[c];
            const float4 v = vreg[c];
            const int k = c * 128 + lane * 4;
#pragma unroll
            for (int e = 0; e < 16; e++) {
                float4 bb = *(const float4*)(eb + e * Hd + k);
                acc[e] = fmaf(tanha(a.x + bb.x), v.x, acc[e]);
                acc[e] = fmaf(tanha(a.y + bb.y), v.y, acc[e]);
                acc[e] = fmaf(tanha(a.z + bb.z), v.z, acc[e]);
                acc[e] = fmaf(tanha(a.w + bb.w), v.w, acc[e]);
            }
        }

#pragma unroll
        for (int e = 0; e < 16; e++) {
#pragma unroll
            for (int off = 16; off > 0; off >>= 1)
                acc[e] += __shfl_xor_sync(0xFFFFFFFFu, acc[e], off);
        }

        if (lane == 0) {
            const size_t half = (size_t)Bn * DECn * ENCn;
            const size_t idx0 = ((size_t)(b * DECn + dt + wid)) * ENCn + et;
#pragma unroll
            for (int q = 0; q < 4; q++) {
                float4 m = *(const float4*)(mask + idx0 + q * 4);
                float4 r = make_float4(acc[q*4], acc[q*4+1], acc[q*4+2], acc[q*4+3]);
                *(float4*)(out + idx0 + q * 4) =
                    make_float4(r.x + m.x, r.y + m.y, r.z + m.z, r.w + m.w);
                *(float4*)(out + half + idx0 + q * 4) = r;
            }
        }
    }
}

// ---------------------------------------------------------------------------
extern "C" void kernel_launch(void* const* d_in, const int* in_sizes, int n_in,
                              void* d_out, int out_size)
{
    const float* dec  = (const float*)d_in[0];
    const float* enc  = (const float*)d_in[1];
    const float* mask = (const float*)d_in[2];
    const float* W1   = (const float*)d_in[3];
    const float* W2   = (const float*)d_in[4];
    const float* vt   = (const float*)d_in[5];
    float* out = (float*)d_out;

    float *enc_t_p, *dec_t_p;
    __nv_bfloat16 *insp_p, *w1t_p, *w2t_p;
    cudaGetSymbolAddress((void**)&enc_t_p, g_enc_t);
    cudaGetSymbolAddress((void**)&dec_t_p, g_dec_t);
    cudaGetSymbolAddress((void**)&insp_p, g_in_split);
    cudaGetSymbolAddress((void**)&w1t_p, g_w1t);
    cudaGetSymbolAddress((void**)&w2t_p, g_w2t);

    int nsm = 148;
    cudaDeviceGetAttribute(&nsm, cudaDevAttrMultiProcessorCount, 0);

    prep_kernel<<<NB_SPLIT + 2 * NB_WT, 256>>>(enc, dec, W1, W2, insp_p, w1t_p, w2t_p);

    cudaFuncSetAttribute(gemm_tc_mma, cudaFuncAttributeMaxDynamicSharedMemorySize, GEMM_SMEM);
    gemm_tc_mma<<<dim3(Hd / 128, MROWS / 128), 256, GEMM_SMEM>>>(
        insp_p, w1t_p, w2t_p, enc_t_p, dec_t_p);

    cudaFuncSetAttribute(score_kernel, cudaFuncAttributeMaxDynamicSharedMemorySize, SC_SMEM);
    score_kernel<<<nsm, 512, SC_SMEM>>>(enc_t_p, dec_t_p, mask, vt, out);
}